// round 4
// baseline (speedup 1.0000x reference)
#include <cuda_runtime.h>

#define B_ 1024
#define F_ 512
#define H_ 1024
#define S_ 8
#define BOX_ 12
#define MAXB_ 64
#define MAXSY_ 64
#define L_ 126
#define G_ 256
#define NT_ 128
#define BK 16
#define AST 68     // As row stride (floats): 64 + pad, 272B = 17*16
#define WST 132    // Ws row stride (floats): 128 dup + pad, 528B = 33*16

__device__ float g_stack[4][B_ * F_];
__device__ float g_h[B_ * H_];
__device__ float g_box[MAXB_][B_ * BOX_];
__device__ float g_sym[MAXSY_][B_ * S_];
__device__ unsigned g_cnt = 0;
__device__ unsigned g_gen = 0;

typedef unsigned long long u64;

__device__ __forceinline__ void ffma2(u64& d, u64 a, u64 b) {
    asm("fma.rn.f32x2 %0,%1,%2,%0;" : "+l"(d) : "l"(a), "l"(b));
}
__device__ __forceinline__ float2 up2(u64 v) {
    float2 r; asm("mov.b64 {%0,%1},%2;" : "=f"(r.x), "=f"(r.y) : "l"(v)); return r;
}
// tanh(x) = 1 - 2/(e^{2x}+1): exact identity, only MUFU rounding (~1e-6 rel)
__device__ __forceinline__ float fast_tanh(float x) {
    float e, r;
    asm("ex2.approx.f32 %0,%1;" : "=f"(e) : "f"(x * 2.8853900817779268f));
    asm("rcp.approx.f32 %0,%1;" : "=f"(r) : "f"(e + 1.0f));
    return fmaf(-2.0f, r, 1.0f);
}

// grid barrier: all G_ blocks resident (128 thr, >=2 blocks/SM -> 296 slots >= 256)
__device__ __forceinline__ void gsync() {
    __syncthreads();
    if (threadIdx.x == 0) {
        volatile unsigned* gen = &g_gen;
        unsigned g = *gen;
        __threadfence();
        if (atomicAdd(&g_cnt, 1u) == G_ - 1u) {
            g_cnt = 0;
            __threadfence();
            *gen = g + 1u;
        } else {
            while (*gen == g) { __nanosleep(64); }
        }
        __threadfence();
    }
    __syncthreads();
}

// C[m0..+64, n0..+64) = tanh(A·Wᵀ + bias). A:[MxK], W:[Nv x K] row-major.
// 128 threads, 8m x 4n microtile, f32x2 accumulators, double-buffered smem.
__device__ __noinline__ void gemm_tile(
    const float* __restrict__ A, const float* __restrict__ W,
    const float* __restrict__ bias, float* __restrict__ C,
    int K, int Nv, int ldc, int m0, int n0)
{
    __shared__ __align__(16) float As[2][BK][AST];
    __shared__ __align__(16) float Ws[2][BK][WST];

    const int tid = threadIdx.x;
    const int mA0 = (tid & 7) * 4;      // m rows mA0..+3 and mA0+32..+35
    const int tn0 = (tid >> 3) * 4;     // 4 n columns

    // loaders: 64 rows x 2 k-halves
    const int lr = tid >> 1;
    const int kh = (tid & 1) * 8;
    const float* Ap = A + (size_t)(m0 + lr) * K + kh;
    const bool wv = (n0 + lr) < Nv;
    const float* Wp = W + (size_t)(n0 + lr) * K + kh;

    u64 acc[4][4];
#pragma unroll
    for (int j = 0; j < 4; ++j)
#pragma unroll
        for (int p = 0; p < 4; ++p) acc[j][p] = 0ull;

    const int P = K / BK;
    float4 a0 = *(const float4*)Ap;
    float4 a1 = *(const float4*)(Ap + 4);
    float4 w0 = wv ? *(const float4*)Wp       : make_float4(0.f, 0.f, 0.f, 0.f);
    float4 w1 = wv ? *(const float4*)(Wp + 4) : make_float4(0.f, 0.f, 0.f, 0.f);

    // stage panel 0 -> buffer 0
    {
        As[0][kh+0][lr]=a0.x; As[0][kh+1][lr]=a0.y; As[0][kh+2][lr]=a0.z; As[0][kh+3][lr]=a0.w;
        As[0][kh+4][lr]=a1.x; As[0][kh+5][lr]=a1.y; As[0][kh+6][lr]=a1.z; As[0][kh+7][lr]=a1.w;
        *(float2*)&Ws[0][kh+0][2*lr]=make_float2(w0.x,w0.x);
        *(float2*)&Ws[0][kh+1][2*lr]=make_float2(w0.y,w0.y);
        *(float2*)&Ws[0][kh+2][2*lr]=make_float2(w0.z,w0.z);
        *(float2*)&Ws[0][kh+3][2*lr]=make_float2(w0.w,w0.w);
        *(float2*)&Ws[0][kh+4][2*lr]=make_float2(w1.x,w1.x);
        *(float2*)&Ws[0][kh+5][2*lr]=make_float2(w1.y,w1.y);
        *(float2*)&Ws[0][kh+6][2*lr]=make_float2(w1.z,w1.z);
        *(float2*)&Ws[0][kh+7][2*lr]=make_float2(w1.w,w1.w);
    }
    __syncthreads();

    for (int p = 0; p < P; ++p) {
        const int cur = p & 1;
        const bool more = (p + 1) < P;
        if (more) {   // global prefetch of next panel
            const int ko = (p + 1) * BK;
            a0 = *(const float4*)(Ap + ko);
            a1 = *(const float4*)(Ap + ko + 4);
            w0 = wv ? *(const float4*)(Wp + ko)     : make_float4(0.f,0.f,0.f,0.f);
            w1 = wv ? *(const float4*)(Wp + ko + 4) : make_float4(0.f,0.f,0.f,0.f);
        }
#pragma unroll
        for (int k = 0; k < BK; ++k) {
            ulonglong2 x0 = *(const ulonglong2*)&As[cur][k][mA0];
            ulonglong2 x1 = *(const ulonglong2*)&As[cur][k][mA0 + 32];
            ulonglong2 y0 = *(const ulonglong2*)&Ws[cur][k][2 * tn0];
            ulonglong2 y1 = *(const ulonglong2*)&Ws[cur][k][2 * tn0 + 4];
            ffma2(acc[0][0],x0.x,y0.x); ffma2(acc[0][1],x0.y,y0.x);
            ffma2(acc[0][2],x1.x,y0.x); ffma2(acc[0][3],x1.y,y0.x);
            ffma2(acc[1][0],x0.x,y0.y); ffma2(acc[1][1],x0.y,y0.y);
            ffma2(acc[1][2],x1.x,y0.y); ffma2(acc[1][3],x1.y,y0.y);
            ffma2(acc[2][0],x0.x,y1.x); ffma2(acc[2][1],x0.y,y1.x);
            ffma2(acc[2][2],x1.x,y1.x); ffma2(acc[2][3],x1.y,y1.x);
            ffma2(acc[3][0],x0.x,y1.y); ffma2(acc[3][1],x0.y,y1.y);
            ffma2(acc[3][2],x1.x,y1.y); ffma2(acc[3][3],x1.y,y1.y);
        }
        if (more) {
            const int nb = cur ^ 1;
            As[nb][kh+0][lr]=a0.x; As[nb][kh+1][lr]=a0.y; As[nb][kh+2][lr]=a0.z; As[nb][kh+3][lr]=a0.w;
            As[nb][kh+4][lr]=a1.x; As[nb][kh+5][lr]=a1.y; As[nb][kh+6][lr]=a1.z; As[nb][kh+7][lr]=a1.w;
            *(float2*)&Ws[nb][kh+0][2*lr]=make_float2(w0.x,w0.x);
            *(float2*)&Ws[nb][kh+1][2*lr]=make_float2(w0.y,w0.y);
            *(float2*)&Ws[nb][kh+2][2*lr]=make_float2(w0.z,w0.z);
            *(float2*)&Ws[nb][kh+3][2*lr]=make_float2(w0.w,w0.w);
            *(float2*)&Ws[nb][kh+4][2*lr]=make_float2(w1.x,w1.x);
            *(float2*)&Ws[nb][kh+5][2*lr]=make_float2(w1.y,w1.y);
            *(float2*)&Ws[nb][kh+6][2*lr]=make_float2(w1.z,w1.z);
            *(float2*)&Ws[nb][kh+7][2*lr]=make_float2(w1.w,w1.w);
        }
        __syncthreads();
    }

    // epilogue: bias + tanh + paired STG.64 along n
#pragma unroll
    for (int jj = 0; jj < 4; jj += 2) {
        const int col = n0 + tn0 + jj;
        if (col < Nv) {
            const float b0 = __ldg(&bias[col]);
            const float b1 = __ldg(&bias[col + 1]);
#pragma unroll
            for (int p = 0; p < 4; ++p) {
                const int r = m0 + ((p < 2) ? (mA0 + 2 * p) : (mA0 + 32 + 2 * (p - 2)));
                float2 vj = up2(acc[jj][p]);
                float2 vk = up2(acc[jj + 1][p]);
                *(float2*)&C[(size_t)r * ldc + col] =
                    make_float2(fast_tanh(vj.x + b0), fast_tanh(vk.x + b1));
                *(float2*)&C[(size_t)(r + 1) * ldc + col] =
                    make_float2(fast_tanh(vj.y + b0), fast_tanh(vk.y + b1));
            }
        }
    }
}

__global__ __launch_bounds__(NT_, 2)
void k_persist(const float* __restrict__ x, const int* __restrict__ ops,
               const float* __restrict__ Wd,  const float* __restrict__ bd,
               const float* __restrict__ Wl,  const float* __restrict__ bl,
               const float* __restrict__ Wr,  const float* __restrict__ br,
               const float* __restrict__ Wsd, const float* __restrict__ bsd,
               const float* __restrict__ Wsf, const float* __restrict__ bsf,
               const float* __restrict__ Wss, const float* __restrict__ bss,
               const float* __restrict__ Wbox,const float* __restrict__ bbox,
               float* __restrict__ out)
{
    const int id = blockIdx.x;
    for (int i = id * NT_ + threadIdx.x; i < B_ * F_; i += G_ * NT_)
        g_stack[0][i] = x[i];
    gsync();

    int sp = 1, bc = 0, sc = 0;
    for (int t = 0; t < L_; ++t) {
        const int op = __ldg(&ops[L_ - 1 - t]);   // processing order (row 0)
        if (op == 1) {
            gemm_tile(g_stack[sp - 1], Wd, bd, g_h, F_, H_, H_,
                      (id >> 4) * 64, (id & 15) * 64);
            gsync();
            if (id < 128)
                gemm_tile(g_h, Wl, bl, g_stack[sp - 1], H_, F_, F_,
                          (id >> 3) * 64, (id & 7) * 64);
            else
                gemm_tile(g_h, Wr, br, g_stack[sp], H_, F_, F_,
                          ((id - 128) >> 3) * 64, ((id - 128) & 7) * 64);
            gsync();
            ++sp;
        } else if (op == 2) {
            gemm_tile(g_stack[sp - 1], Wsd, bsd, g_h, F_, H_, H_,
                      (id >> 4) * 64, (id & 15) * 64);
            gsync();
            if (id < 128)
                gemm_tile(g_h, Wsf, bsf, g_stack[sp - 1], H_, F_, F_,
                          (id >> 3) * 64, (id & 7) * 64);
            else if (id < 144)
                gemm_tile(g_h, Wss, bss, g_sym[sc], H_, S_, S_,
                          (id - 128) * 64, 0);
            gsync();
            ++sc;
        } else {
            // pop: box[bc] = tanh(Wbox·top + bbox). 4 warps, 1 row/warp.
            const int w = threadIdx.x >> 5, lane = threadIdx.x & 31;
            const int row = id * 4 + w;
            const float* tr = g_stack[sp - 1] + (size_t)row * F_;
            float xv[F_ / 32];
#pragma unroll
            for (int i = 0; i < F_ / 32; ++i) xv[i] = tr[lane + 32 * i];
            for (int c = 0; c < BOX_; ++c) {
                const float* wr = Wbox + (size_t)c * F_;
                float s = 0.f;
#pragma unroll
                for (int i = 0; i < F_ / 32; ++i)
                    s = fmaf(xv[i], __ldg(&wr[lane + 32 * i]), s);
#pragma unroll
                for (int off = 16; off > 0; off >>= 1)
                    s += __shfl_xor_sync(0xffffffffu, s, off);
                if (lane == 0)
                    g_box[bc][row * BOX_ + c] = fast_tanh(s + __ldg(&bbox[c]));
            }
            ++bc; --sp;   // next phase's gsync (after stage A) orders everything
        }
    }
    gsync();

    // emit: boxes [B,64,12] then syms [B,64,8], reversed + zero-padded
    const int NBOX = B_ * MAXB_ * BOX_;
    const int NSYM = B_ * MAXSY_ * S_;
    for (int idx = id * NT_ + threadIdx.x; idx < NBOX + NSYM; idx += G_ * NT_) {
        if (idx < NBOX) {
            int b = idx / (MAXB_ * BOX_);
            int r = idx % (MAXB_ * BOX_);
            int j = r / BOX_, c = r % BOX_;
            out[idx] = (j < bc) ? g_box[bc - 1 - j][b * BOX_ + c] : 0.f;
        } else {
            int i2 = idx - NBOX;
            int b = i2 / (MAXSY_ * S_);
            int r = i2 % (MAXSY_ * S_);
            int j = r / S_, c = r % S_;
            out[idx] = (j < sc) ? g_sym[sc - 1 - j][b * S_ + c] : 0.f;
        }
    }
}

extern "C" void kernel_launch(void* const* d_in, const int* in_sizes, int n_in,
                              void* d_out, int out_size) {
    (void)in_sizes; (void)n_in; (void)out_size;
    k_persist<<<G_, NT_>>>(
        (const float*)d_in[0], (const int*)d_in[1],
        (const float*)d_in[2], (const float*)d_in[3],
        (const float*)d_in[4], (const float*)d_in[5],
        (const float*)d_in[6], (const float*)d_in[7],
        (const float*)d_in[8], (const float*)d_in[9],
        (const float*)d_in[10], (const float*)d_in[11],
        (const float*)d_in[12], (const float*)d_in[13],
        (const float*)d_in[14], (const float*)d_in[15],
        (float*)d_out);
}